// round 10
// baseline (speedup 1.0000x reference)
#include <cuda_runtime.h>
#include <math.h>

// ---------------------------------------------------------------------------
// PGA(3,0,1) blade algebra, computed at compile time.
// Blade order: 0:() 1:e0 2:e1 3:e2 4:e3 5:e01 6:e02 7:e03 8:e12 9:e13 10:e23
//              11:e012 12:e013 13:e023 14:e123 15:e0123
// ---------------------------------------------------------------------------

__host__ __device__ constexpr int pc4(int x) {
    return ((x >> 0) & 1) + ((x >> 1) & 1) + ((x >> 2) & 1) + ((x >> 3) & 1);
}

__host__ __device__ constexpr int I2M(int i) {
    return (i == 0) ? 0  : (i == 1) ? 1  : (i == 2) ? 2  : (i == 3) ? 4  :
           (i == 4) ? 8  : (i == 5) ? 3  : (i == 6) ? 5  : (i == 7) ? 9  :
           (i == 8) ? 6  : (i == 9) ? 10 : (i == 10) ? 12 : (i == 11) ? 7 :
           (i == 12) ? 11 : (i == 13) ? 13 : (i == 14) ? 14 : 15;
}

__host__ __device__ constexpr int M2I(int m) {
    return (m == 0) ? 0  : (m == 1) ? 1  : (m == 2) ? 2  : (m == 3) ? 5  :
           (m == 4) ? 3  : (m == 5) ? 6  : (m == 6) ? 8  : (m == 7) ? 11 :
           (m == 8) ? 4  : (m == 9) ? 7  : (m == 10) ? 9 : (m == 11) ? 12 :
           (m == 12) ? 10 : (m == 13) ? 13 : (m == 14) ? 14 : 15;
}

__host__ __device__ constexpr int msign(int a, int b) {
    int s = 0;
    if ((b >> 0) & 1) s += pc4(a >> 1);
    if ((b >> 1) & 1) s += pc4(a >> 2);
    if ((b >> 2) & 1) s += pc4(a >> 3);
    return (s & 1) ? -1 : 1;
}

__host__ __device__ constexpr int dsign(int m) { return msign(m, 15 ^ m); }

__host__ __device__ constexpr int jsign(int ma, int mb) {
    return dsign(ma) * dsign(mb) * msign(15 ^ ma, 15 ^ mb) * dsign(ma & mb);
}

// ---------------------------------------------------------------------------
// Compile-time unroll driver (all indices constexpr -> literal subscripts).
// ---------------------------------------------------------------------------
template<int I> struct IC { static constexpr int v = I; };

template<int N> struct Unroll {
    template<typename F>
    __device__ __forceinline__ static void run(F&& f) {
        Unroll<N - 1>::run(f);
        f(IC<N - 1>{});
    }
};
template<> struct Unroll<0> {
    template<typename F>
    __device__ __forceinline__ static void run(F&&) {}
};

// ---------------------------------------------------------------------------
// Half-split: warp with (wid&1)==H computes output blades d in [8H, 8H+8).
// Every e0-blade output's V-path source index lives in the same half.
// ---------------------------------------------------------------------------

template<int H>
__device__ __forceinline__ void compute_half(
    const float xn[16],
    const float W1f[5], const float V1f[4], float u0,
    const float WG[5], const float VG[4],
    const float WJ[5], const float VJ[4],
    float biases, float o[8])
{
    float gp[8], jn[8];
    Unroll<8>::run([&](auto K) {
        constexpr int k = decltype(K)::v;
        gp[k] = 0.f; jn[k] = 0.f;
    });

    Unroll<16>::run([&](auto J) {
        constexpr int j  = decltype(J)::v;
        constexpr int mb = I2M(j);
        constexpr int gB = pc4(mb);

        float uj;
        if constexpr (j == 0) {
            uj = u0;
        } else {
            uj = W1f[gB] * xn[j];
            if constexpr ((mb & 1) && gB < 4)
                uj = fmaf(V1f[gB], xn[M2I(mb ^ 1)], uj);
        }

        Unroll<16>::run([&](auto I_) {
            constexpr int i  = decltype(I_)::v;
            constexpr int ma = I2M(i);
            if constexpr (!(ma & mb & 1)) {                 // e0^2 = 0
                constexpr int k = M2I(ma ^ mb);
                if constexpr (k >= 8 * H && k < 8 * H + 8) {
                    if constexpr (msign(ma, mb) > 0)
                        gp[k - 8 * H] = fmaf(xn[i],  uj, gp[k - 8 * H]);
                    else
                        gp[k - 8 * H] = fmaf(xn[i], -uj, gp[k - 8 * H]);
                }
            }
            if constexpr ((ma | mb) == 15) {                // join support
                constexpr int k = M2I(ma & mb);
                if constexpr (k >= 8 * H && k < 8 * H + 8) {
                    if constexpr (jsign(ma, mb) > 0)
                        jn[k - 8 * H] = fmaf(xn[i],  uj, jn[k - 8 * H]);
                    else
                        jn[k - 8 * H] = fmaf(xn[i], -uj, jn[k - 8 * H]);
                }
            }
        });
    });

    Unroll<8>::run([&](auto DD) {
        constexpr int dd = decltype(DD)::v;
        constexpr int d  = 8 * H + dd;
        constexpr int m  = I2M(d);
        constexpr int g  = pc4(m);
        float v = fmaf(WG[g], gp[dd], xn[d]);               // residual = raw x
        v = fmaf(WJ[g], jn[dd], v);
        if constexpr ((m & 1) && g < 4) {
            constexpr int sidx = M2I(m ^ 1) - 8 * H;        // same half
            v = fmaf(VG[g], gp[sidx], v);
            v = fmaf(VJ[g], jn[sidx], v);
        }
        if constexpr (H == 0 && dd == 0) v += biases;
        o[dd] = v;
    });
}

// ---------------------------------------------------------------------------
// 256 threads / block, 128 tokens / block. Token tloc = (wid>>1)*32 + lane,
// half = wid & 1 (warp-uniform). Coalesced global I/O via swizzled smem.
// __launch_bounds__(256, 6): cap regs (~42) to lift occupancy to ~48 warps/SM;
// the small spill set this causes is latency-hidden by the extra warps.
// ---------------------------------------------------------------------------
#define TPB      256
#define TOKS_BLK 128

__device__ __forceinline__ int swz(int t, int c) {
    return 4 * t + (c ^ ((t >> 1) & 3));
}

__global__ void __launch_bounds__(TPB, 6)
mvffn_kernel(const float* __restrict__ x,
             const float* __restrict__ w1, const float* __restrict__ v1, const float* __restrict__ b1,
             const float* __restrict__ wg, const float* __restrict__ vg, const float* __restrict__ bg,
             const float* __restrict__ wj, const float* __restrict__ vj, const float* __restrict__ bj,
             float* __restrict__ out, int ntok)
{
    __shared__ float4 stage[TOKS_BLK * 4];

    const int tid  = threadIdx.x;
    const int base = blockIdx.x * TOKS_BLK;
    const float4* xin4 = reinterpret_cast<const float4*>(x)  + (size_t)base * 4;
    float4*       out4 = reinterpret_cast<float4*>(out)      + (size_t)base * 4;
    const int     nf4  = min(TOKS_BLK, ntok - base) * 4;

    // ---- coalesced load -> swizzled smem (512 float4 = 2 iters) ----
    #pragma unroll
    for (int k = 0; k < 2; k++) {
        int f = tid + k * TPB;
        if (f < nf4) stage[swz(f >> 2, f & 3)] = xin4[f];
    }
    __syncthreads();

    const int wid  = tid >> 5;
    const int lane = tid & 31;
    const int tloc = (wid >> 1) * 32 + lane;    // 0..127
    const int half = wid & 1;                   // warp-uniform
    const bool active = (base + tloc < ntok);

    if (active) {
        float4 q0 = stage[swz(tloc, 0)], q1 = stage[swz(tloc, 1)];
        float4 q2 = stage[swz(tloc, 2)], q3 = stage[swz(tloc, 3)];

        // RAW x — also the residual (normalization folded into out-weights).
        float xn[16] = { q0.x, q0.y, q0.z, q0.w,
                         q1.x, q1.y, q1.z, q1.w,
                         q2.x, q2.y, q2.z, q2.w,
                         q3.x, q3.y, q3.z, q3.w };

        // ---- norm factors over non-e0 blades: idx 0,2,3,4,8,9,10,14 ----
        float s = 1e-5f;
        s = fmaf(xn[0],  xn[0],  s);
        s = fmaf(xn[2],  xn[2],  s);
        s = fmaf(xn[3],  xn[3],  s);
        s = fmaf(xn[4],  xn[4],  s);
        s = fmaf(xn[8],  xn[8],  s);
        s = fmaf(xn[9],  xn[9],  s);
        s = fmaf(xn[10], xn[10], s);
        s = fmaf(xn[14], xn[14], s);
        const float rinv  = rsqrtf(s);
        const float rinv2 = rinv * rinv;
        const float rinv3 = rinv2 * rinv;
        const float nrm   = s * rinv;            // sqrt(s)

        // ---- gate ----
        const float4 w1a = *reinterpret_cast<const float4*>(w1);
        const float  w1e = w1[4];
        const float4 v1a = *reinterpret_cast<const float4*>(v1);

        const float xp0 = fmaf(w1a.x, xn[0] * rinv, b1[0]);
        const float G   = xp0 * normcdff(xp0);   // exact GELU

        const float W1f[5] = { G * w1a.x, G * w1a.y, G * w1a.z, G * w1a.w, G * w1e };
        const float V1f[4] = { G * v1a.x, G * v1a.y, G * v1a.z, G * v1a.w };
        const float u0 = (G * xp0) * nrm;        // homogenize bias column

        // ---- output weights with normalization folded in ----
        const float4 wga = *reinterpret_cast<const float4*>(wg);
        const float  wge = wg[4];
        const float4 vga = *reinterpret_cast<const float4*>(vg);
        const float4 wja = *reinterpret_cast<const float4*>(wj);
        const float  wje = wj[4];
        const float4 vja = *reinterpret_cast<const float4*>(vj);

        const float gfac = rinv2;                // gp path scale
        const float jfac = xn[15] * rinv3;       // join path scale

        const float WG[5] = { wga.x * gfac, wga.y * gfac, wga.z * gfac,
                              wga.w * gfac, wge * gfac };
        const float VG[4] = { vga.x * gfac, vga.y * gfac, vga.z * gfac,
                              vga.w * gfac };
        const float WJ[5] = { wja.x * jfac, wja.y * jfac, wja.z * jfac,
                              wja.w * jfac, wje * jfac };
        const float VJ[4] = { vja.x * jfac, vja.y * jfac, vja.z * jfac,
                              vja.w * jfac };

        const float biases = bg[0] + bj[0];

        float o[8];
        if (half == 0)
            compute_half<0>(xn, W1f, V1f, u0, WG, VG, WJ, VJ, biases, o);
        else
            compute_half<1>(xn, W1f, V1f, u0, WG, VG, WJ, VJ, biases, o);

        // write this half's 8 outputs (chunks 2*half, 2*half+1)
        stage[swz(tloc, 2 * half)]     = make_float4(o[0], o[1], o[2], o[3]);
        stage[swz(tloc, 2 * half + 1)] = make_float4(o[4], o[5], o[6], o[7]);
    }
    __syncthreads();

    // ---- coalesced store from swizzled smem ----
    #pragma unroll
    for (int k = 0; k < 2; k++) {
        int f = tid + k * TPB;
        if (f < nf4) out4[f] = stage[swz(f >> 2, f & 3)];
    }
}

extern "C" void kernel_launch(void* const* d_in, const int* in_sizes, int n_in,
                              void* d_out, int out_size)
{
    const float* x  = (const float*)d_in[0];
    const float* w1 = (const float*)d_in[1];
    const float* v1 = (const float*)d_in[2];
    const float* b1 = (const float*)d_in[3];
    const float* wg = (const float*)d_in[4];
    const float* vg = (const float*)d_in[5];
    const float* bg = (const float*)d_in[6];
    const float* wj = (const float*)d_in[7];
    const float* vj = (const float*)d_in[8];
    const float* bj = (const float*)d_in[9];

    const int ntok   = in_sizes[0] / 16;
    const int blocks = (ntok + TOKS_BLK - 1) / TOKS_BLK;

    mvffn_kernel<<<blocks, TPB>>>(x, w1, v1, b1, wg, vg, bg, wj, vj, bj,
                                  (float*)d_out, ntok);
}

// round 11
// speedup vs baseline: 1.2924x; 1.2924x over previous
#include <cuda_runtime.h>
#include <math.h>

// ---------------------------------------------------------------------------
// PGA(3,0,1) blade algebra, computed at compile time.
// Blade order: 0:() 1:e0 2:e1 3:e2 4:e3 5:e01 6:e02 7:e03 8:e12 9:e13 10:e23
//              11:e012 12:e013 13:e023 14:e123 15:e0123
// ---------------------------------------------------------------------------

__host__ __device__ constexpr int pc4(int x) {
    return ((x >> 0) & 1) + ((x >> 1) & 1) + ((x >> 2) & 1) + ((x >> 3) & 1);
}

__host__ __device__ constexpr int I2M(int i) {
    return (i == 0) ? 0  : (i == 1) ? 1  : (i == 2) ? 2  : (i == 3) ? 4  :
           (i == 4) ? 8  : (i == 5) ? 3  : (i == 6) ? 5  : (i == 7) ? 9  :
           (i == 8) ? 6  : (i == 9) ? 10 : (i == 10) ? 12 : (i == 11) ? 7 :
           (i == 12) ? 11 : (i == 13) ? 13 : (i == 14) ? 14 : 15;
}

__host__ __device__ constexpr int M2I(int m) {
    return (m == 0) ? 0  : (m == 1) ? 1  : (m == 2) ? 2  : (m == 3) ? 5  :
           (m == 4) ? 3  : (m == 5) ? 6  : (m == 6) ? 8  : (m == 7) ? 11 :
           (m == 8) ? 4  : (m == 9) ? 7  : (m == 10) ? 9 : (m == 11) ? 12 :
           (m == 12) ? 10 : (m == 13) ? 13 : (m == 14) ? 14 : 15;
}

__host__ __device__ constexpr int msign(int a, int b) {
    int s = 0;
    if ((b >> 0) & 1) s += pc4(a >> 1);
    if ((b >> 1) & 1) s += pc4(a >> 2);
    if ((b >> 2) & 1) s += pc4(a >> 3);
    return (s & 1) ? -1 : 1;
}

__host__ __device__ constexpr int dsign(int m) { return msign(m, 15 ^ m); }

__host__ __device__ constexpr int jsign(int ma, int mb) {
    return dsign(ma) * dsign(mb) * msign(15 ^ ma, 15 ^ mb) * dsign(ma & mb);
}

// ---------------------------------------------------------------------------
// Compile-time unroll driver (all indices constexpr -> literal subscripts).
// ---------------------------------------------------------------------------
template<int I> struct IC { static constexpr int v = I; };

template<int N> struct Unroll {
    template<typename F>
    __device__ __forceinline__ static void run(F&& f) {
        Unroll<N - 1>::run(f);
        f(IC<N - 1>{});
    }
};
template<> struct Unroll<0> {
    template<typename F>
    __device__ __forceinline__ static void run(F&&) {}
};

// ---------------------------------------------------------------------------
// Full per-token computation (R7 formulation: bilinear on RAW x, all
// normalization folded into the output-weight scalars). Inlined twice per
// thread to create two independent FFMA streams (2x per-warp ILP).
// ---------------------------------------------------------------------------
struct Wts {
    float w10, w11, w12, w13, w14;
    float v10, v11, v12, v13;
    float b1s;
    float wg0, wg1, wg2, wg3, wg4;
    float vg0, vg1, vg2, vg3;
    float wj0, wj1, wj2, wj3, wj4;
    float vj0, vj1, vj2, vj3;
    float bias;   // bg + bj
};

__device__ __forceinline__ void compute_token(const float xn[16], const Wts& W,
                                              float o[16])
{
    // ---- norm factors over non-e0 blades: idx 0,2,3,4,8,9,10,14 ----
    float s = 1e-5f;
    s = fmaf(xn[0],  xn[0],  s);
    s = fmaf(xn[2],  xn[2],  s);
    s = fmaf(xn[3],  xn[3],  s);
    s = fmaf(xn[4],  xn[4],  s);
    s = fmaf(xn[8],  xn[8],  s);
    s = fmaf(xn[9],  xn[9],  s);
    s = fmaf(xn[10], xn[10], s);
    s = fmaf(xn[14], xn[14], s);
    const float rinv  = rsqrtf(s);
    const float rinv2 = rinv * rinv;
    const float rinv3 = rinv2 * rinv;
    const float nrm   = s * rinv;            // sqrt(s)

    // ---- gate: xp0 = w1[0]*xn_norm[0] + b1; G = exact GELU ----
    const float xp0 = fmaf(W.w10, xn[0] * rinv, W.b1s);
    const float G   = xp0 * normcdff(xp0);

    const float W1f[5] = { G * W.w10, G * W.w11, G * W.w12, G * W.w13, G * W.w14 };
    const float V1f[4] = { G * W.v10, G * W.v11, G * W.v12, G * W.v13 };
    const float u0 = (G * xp0) * nrm;        // homogenize the bias column

    // ---- bilinear on RAW x ----
    float gp[16], jn[16];
    Unroll<16>::run([&](auto K) {
        constexpr int k = decltype(K)::v;
        gp[k] = 0.f; jn[k] = 0.f;
    });

    Unroll<16>::run([&](auto J) {
        constexpr int j  = decltype(J)::v;
        constexpr int mb = I2M(j);
        constexpr int gB = pc4(mb);

        float uj;
        if constexpr (j == 0) {
            uj = u0;
        } else {
            uj = W1f[gB] * xn[j];
            if constexpr ((mb & 1) && gB < 4)
                uj = fmaf(V1f[gB], xn[M2I(mb ^ 1)], uj);
        }

        Unroll<16>::run([&](auto I_) {
            constexpr int i  = decltype(I_)::v;
            constexpr int ma = I2M(i);
            if constexpr (!(ma & mb & 1)) {            // e0^2 = 0
                constexpr int k = M2I(ma ^ mb);
                if constexpr (msign(ma, mb) > 0) gp[k] = fmaf(xn[i],  uj, gp[k]);
                else                             gp[k] = fmaf(xn[i], -uj, gp[k]);
            }
            if constexpr ((ma | mb) == 15) {           // join support
                constexpr int k = M2I(ma & mb);
                if constexpr (jsign(ma, mb) > 0) jn[k] = fmaf(xn[i],  uj, jn[k]);
                else                             jn[k] = fmaf(xn[i], -uj, jn[k]);
            }
        });
    });

    // ---- output linears with normalization folded into the weights ----
    const float gfac = rinv2;                 // gp path scale
    const float jfac = xn[15] * rinv3;        // join path scale

    const float WG[5] = { W.wg0 * gfac, W.wg1 * gfac, W.wg2 * gfac,
                          W.wg3 * gfac, W.wg4 * gfac };
    const float VG[4] = { W.vg0 * gfac, W.vg1 * gfac, W.vg2 * gfac,
                          W.vg3 * gfac };
    const float WJ[5] = { W.wj0 * jfac, W.wj1 * jfac, W.wj2 * jfac,
                          W.wj3 * jfac, W.wj4 * jfac };
    const float VJ[4] = { W.vj0 * jfac, W.vj1 * jfac, W.vj2 * jfac,
                          W.vj3 * jfac };

    Unroll<16>::run([&](auto D) {
        constexpr int d = decltype(D)::v;
        constexpr int m = I2M(d);
        constexpr int g = pc4(m);
        float v = fmaf(WG[g], gp[d], xn[d]);   // residual = raw x[d]
        v = fmaf(WJ[g], jn[d], v);
        if constexpr ((m & 1) && g < 4) {
            constexpr int sidx = M2I(m ^ 1);
            v = fmaf(VG[g], gp[sidx], v);
            v = fmaf(VJ[g], jn[sidx], v);
        }
        o[d] = v;
    });
    o[0] += W.bias;
}

// ---------------------------------------------------------------------------
// 128 threads / block, 256 tokens / block, 2 independent scalar token streams
// per thread (tokens tid and tid+128). Coalesced global I/O via swizzled smem.
// ---------------------------------------------------------------------------
#define THREADS 128
#define TOKS    256

__device__ __forceinline__ int swz(int t, int c) {
    return 4 * t + (c ^ ((t >> 1) & 3));
}

__global__ void __launch_bounds__(THREADS)
mvffn_kernel(const float* __restrict__ x,
             const float* __restrict__ w1, const float* __restrict__ v1, const float* __restrict__ b1,
             const float* __restrict__ wg, const float* __restrict__ vg, const float* __restrict__ bg,
             const float* __restrict__ wj, const float* __restrict__ vj, const float* __restrict__ bj,
             float* __restrict__ out, int ntok)
{
    __shared__ float4 stage[TOKS * 4];

    const int tid  = threadIdx.x;
    const int base = blockIdx.x * TOKS;
    const float4* xin4 = reinterpret_cast<const float4*>(x)  + (size_t)base * 4;
    float4*       out4 = reinterpret_cast<float4*>(out)      + (size_t)base * 4;
    const int     nf4  = min(TOKS, ntok - base) * 4;

    // ---- coalesced load -> swizzled smem (1024 float4 = 8 iters) ----
    #pragma unroll
    for (int k = 0; k < 8; k++) {
        int f = tid + k * THREADS;
        if (f < nf4) stage[swz(f >> 2, f & 3)] = xin4[f];
    }
    __syncthreads();

    // ---- shared weight loads (vectorized, one copy per thread) ----
    const float4 w1a = *reinterpret_cast<const float4*>(w1);
    const float4 v1a = *reinterpret_cast<const float4*>(v1);
    const float4 wga = *reinterpret_cast<const float4*>(wg);
    const float4 vga = *reinterpret_cast<const float4*>(vg);
    const float4 wja = *reinterpret_cast<const float4*>(wj);
    const float4 vja = *reinterpret_cast<const float4*>(vj);
    Wts W;
    W.w10 = w1a.x; W.w11 = w1a.y; W.w12 = w1a.z; W.w13 = w1a.w; W.w14 = w1[4];
    W.v10 = v1a.x; W.v11 = v1a.y; W.v12 = v1a.z; W.v13 = v1a.w;
    W.b1s = b1[0];
    W.wg0 = wga.x; W.wg1 = wga.y; W.wg2 = wga.z; W.wg3 = wga.w; W.wg4 = wg[4];
    W.vg0 = vga.x; W.vg1 = vga.y; W.vg2 = vga.z; W.vg3 = vga.w;
    W.wj0 = wja.x; W.wj1 = wja.y; W.wj2 = wja.z; W.wj3 = wja.w; W.wj4 = wj[4];
    W.vj0 = vja.x; W.vj1 = vja.y; W.vj2 = vja.z; W.vj3 = vja.w;
    W.bias = bg[0] + bj[0];

    const int tA = base + tid;
    const int tB = tA + THREADS;
    const bool hasA = (tA < ntok);
    const bool hasB = (tB < ntok);

    // Two independent scalar streams; ptxas interleaves them for ILP.
    if (hasA) {
        float xnA[16], oA[16];
        {
            float4 q0 = stage[swz(tid, 0)], q1 = stage[swz(tid, 1)];
            float4 q2 = stage[swz(tid, 2)], q3 = stage[swz(tid, 3)];
            xnA[0]=q0.x; xnA[1]=q0.y; xnA[2]=q0.z; xnA[3]=q0.w;
            xnA[4]=q1.x; xnA[5]=q1.y; xnA[6]=q1.z; xnA[7]=q1.w;
            xnA[8]=q2.x; xnA[9]=q2.y; xnA[10]=q2.z; xnA[11]=q2.w;
            xnA[12]=q3.x; xnA[13]=q3.y; xnA[14]=q3.z; xnA[15]=q3.w;
        }
        float xnB[16], oB[16];
        if (hasB) {
            const int lB = tid + THREADS;
            float4 q0 = stage[swz(lB, 0)], q1 = stage[swz(lB, 1)];
            float4 q2 = stage[swz(lB, 2)], q3 = stage[swz(lB, 3)];
            xnB[0]=q0.x; xnB[1]=q0.y; xnB[2]=q0.z; xnB[3]=q0.w;
            xnB[4]=q1.x; xnB[5]=q1.y; xnB[6]=q1.z; xnB[7]=q1.w;
            xnB[8]=q2.x; xnB[9]=q2.y; xnB[10]=q2.z; xnB[11]=q2.w;
            xnB[12]=q3.x; xnB[13]=q3.y; xnB[14]=q3.z; xnB[15]=q3.w;
        }

        compute_token(xnA, W, oA);
        if (hasB) compute_token(xnB, W, oB);

        stage[swz(tid, 0)] = make_float4(oA[0],  oA[1],  oA[2],  oA[3]);
        stage[swz(tid, 1)] = make_float4(oA[4],  oA[5],  oA[6],  oA[7]);
        stage[swz(tid, 2)] = make_float4(oA[8],  oA[9],  oA[10], oA[11]);
        stage[swz(tid, 3)] = make_float4(oA[12], oA[13], oA[14], oA[15]);
        if (hasB) {
            const int lB = tid + THREADS;
            stage[swz(lB, 0)] = make_float4(oB[0],  oB[1],  oB[2],  oB[3]);
            stage[swz(lB, 1)] = make_float4(oB[4],  oB[5],  oB[6],  oB[7]);
            stage[swz(lB, 2)] = make_float4(oB[8],  oB[9],  oB[10], oB[11]);
            stage[swz(lB, 3)] = make_float4(oB[12], oB[13], oB[14], oB[15]);
        }
    }
    __syncthreads();

    // ---- coalesced store from swizzled smem ----
    #pragma unroll
    for (int k = 0; k < 8; k++) {
        int f = tid + k * THREADS;
        if (f < nf4) out4[f] = stage[swz(f >> 2, f & 3)];
    }
}

extern "C" void kernel_launch(void* const* d_in, const int* in_sizes, int n_in,
                              void* d_out, int out_size)
{
    const float* x  = (const float*)d_in[0];
    const float* w1 = (const float*)d_in[1];
    const float* v1 = (const float*)d_in[2];
    const float* b1 = (const float*)d_in[3];
    const float* wg = (const float*)d_in[4];
    const float* vg = (const float*)d_in[5];
    const float* bg = (const float*)d_in[6];
    const float* wj = (const float*)d_in[7];
    const float* vj = (const float*)d_in[8];
    const float* bj = (const float*)d_in[9];

    const int ntok   = in_sizes[0] / 16;
    const int blocks = (ntok + TOKS - 1) / TOKS;

    mvffn_kernel<<<blocks, THREADS>>>(x, w1, v1, b1, wg, vg, bg, wj, vj, bj,
                                      (float*)d_out, ntok);
}

// round 12
// speedup vs baseline: 1.5608x; 1.2077x over previous
#include <cuda_runtime.h>
#include <math.h>

// ---------------------------------------------------------------------------
// PGA(3,0,1) blade algebra, computed at compile time.
// Blade order: 0:() 1:e0 2:e1 3:e2 4:e3 5:e01 6:e02 7:e03 8:e12 9:e13 10:e23
//              11:e012 12:e013 13:e023 14:e123 15:e0123
// ---------------------------------------------------------------------------

__host__ __device__ constexpr int pc4(int x) {
    return ((x >> 0) & 1) + ((x >> 1) & 1) + ((x >> 2) & 1) + ((x >> 3) & 1);
}

__host__ __device__ constexpr int I2M(int i) {
    return (i == 0) ? 0  : (i == 1) ? 1  : (i == 2) ? 2  : (i == 3) ? 4  :
           (i == 4) ? 8  : (i == 5) ? 3  : (i == 6) ? 5  : (i == 7) ? 9  :
           (i == 8) ? 6  : (i == 9) ? 10 : (i == 10) ? 12 : (i == 11) ? 7 :
           (i == 12) ? 11 : (i == 13) ? 13 : (i == 14) ? 14 : 15;
}

__host__ __device__ constexpr int M2I(int m) {
    return (m == 0) ? 0  : (m == 1) ? 1  : (m == 2) ? 2  : (m == 3) ? 5  :
           (m == 4) ? 3  : (m == 5) ? 6  : (m == 6) ? 8  : (m == 7) ? 11 :
           (m == 8) ? 4  : (m == 9) ? 7  : (m == 10) ? 9 : (m == 11) ? 12 :
           (m == 12) ? 10 : (m == 13) ? 13 : (m == 14) ? 14 : 15;
}

__host__ __device__ constexpr int msign(int a, int b) {
    int s = 0;
    if ((b >> 0) & 1) s += pc4(a >> 1);
    if ((b >> 1) & 1) s += pc4(a >> 2);
    if ((b >> 2) & 1) s += pc4(a >> 3);
    return (s & 1) ? -1 : 1;
}

__host__ __device__ constexpr int dsign(int m) { return msign(m, 15 ^ m); }

__host__ __device__ constexpr int jsign(int ma, int mb) {
    return dsign(ma) * dsign(mb) * msign(15 ^ ma, 15 ^ mb) * dsign(ma & mb);
}

// ---------------------------------------------------------------------------
// Compile-time unroll driver (all indices constexpr -> literal subscripts).
// ---------------------------------------------------------------------------
template<int I> struct IC { static constexpr int v = I; };

template<int N> struct Unroll {
    template<typename F>
    __device__ __forceinline__ static void run(F&& f) {
        Unroll<N - 1>::run(f);
        f(IC<N - 1>{});
    }
};
template<> struct Unroll<0> {
    template<typename F>
    __device__ __forceinline__ static void run(F&&) {}
};

// ---------------------------------------------------------------------------
// Branch-free Phi(x) (standard normal CDF) via Abramowitz-Stegun 7.1.26 erf:
//   erf(z) = 1 - (((((a5 t + a4) t + a3) t + a2) t + a1) t) * exp(-z^2),
//   t = 1/(1 + p z), z >= 0;  max abs error 1.5e-7.
// Sign handled with fabs/copysign (no divergence). 2 MUFU + ~10 FFMA.
// ---------------------------------------------------------------------------
__device__ __forceinline__ float phi_cdf(float x) {
    const float z  = fabsf(x) * 0.70710678118654752f;   // |x|/sqrt(2)
    const float t  = __frcp_rn(fmaf(0.3275911f, z, 1.0f));
    float p = fmaf(1.061405429f, t, -1.453152027f);
    p = fmaf(p, t,  1.421413741f);
    p = fmaf(p, t, -0.284496736f);
    p = fmaf(p, t,  0.254829592f);
    p = p * t;
    const float e   = __expf(-z * z);                   // MUFU EX2 path
    const float erf = 1.0f - p * e;                     // erf(|x|/sqrt2)
    const float se  = copysignf(erf, x);
    return fmaf(0.5f, se, 0.5f);                        // 0.5*(1+erf(x/sqrt2))
}

// ---------------------------------------------------------------------------
// One thread per token; 256 threads / block; coalesced global I/O staged
// through a swizzled smem buffer. Bilinear on RAW x, normalization folded
// into output-weight scalars (R7 formulation). FULL=true drops bounds checks
// (used when ntok is an exact multiple of TPB).
// ---------------------------------------------------------------------------
#define TPB 256

__device__ __forceinline__ int swz(int t, int c) {
    return 4 * t + (c ^ ((t >> 1) & 3));
}

template<bool FULL>
__global__ void __launch_bounds__(TPB)
mvffn_kernel(const float* __restrict__ x,
             const float* __restrict__ w1, const float* __restrict__ v1, const float* __restrict__ b1,
             const float* __restrict__ wg, const float* __restrict__ vg, const float* __restrict__ bg,
             const float* __restrict__ wj, const float* __restrict__ vj, const float* __restrict__ bj,
             float* __restrict__ out, int ntok)
{
    __shared__ float4 stage[TPB * 4];

    const int tid  = threadIdx.x;
    const int base = blockIdx.x * TPB;
    const float4* xin4 = reinterpret_cast<const float4*>(x)  + (size_t)base * 4;
    float4*       out4 = reinterpret_cast<float4*>(out)      + (size_t)base * 4;
    const int     nf4  = FULL ? TPB * 4 : min(TPB, ntok - base) * 4;

    // ---- coalesced load -> swizzled smem ----
    #pragma unroll
    for (int k = 0; k < 4; k++) {
        int f = tid + k * TPB;
        if (FULL || f < nf4) stage[swz(f >> 2, f & 3)] = xin4[f];
    }
    __syncthreads();

    if (FULL || base + tid < ntok) {
        float4 q0 = stage[swz(tid, 0)], q1 = stage[swz(tid, 1)];
        float4 q2 = stage[swz(tid, 2)], q3 = stage[swz(tid, 3)];

        // RAW x — also the residual.
        float xn[16] = { q0.x, q0.y, q0.z, q0.w,
                         q1.x, q1.y, q1.z, q1.w,
                         q2.x, q2.y, q2.z, q2.w,
                         q3.x, q3.y, q3.z, q3.w };

        // ---- norm sum (tree-reduced: serial depth 3 FMAs + 2 ADDs) ----
        float sa = fmaf(xn[0],  xn[0],  1e-5f);
        sa       = fmaf(xn[2],  xn[2],  sa);
        float sb = xn[3] * xn[3];
        sb       = fmaf(xn[4],  xn[4],  sb);
        float sc = xn[8] * xn[8];
        sc       = fmaf(xn[9],  xn[9],  sc);
        float sd = xn[10] * xn[10];
        sd       = fmaf(xn[14], xn[14], sd);
        const float s = (sa + sb) + (sc + sd);

        const float rinv  = rsqrtf(s);
        const float rinv2 = rinv * rinv;
        const float rinv3 = rinv2 * rinv;
        const float nrm   = s * rinv;            // sqrt(s)

        // ---- gate: xp0 = w1[0]*xn_norm[0] + b1; G = exact-accuracy GELU ----
        const float4 w1a = *reinterpret_cast<const float4*>(w1);
        const float  w1e = w1[4];
        const float4 v1a = *reinterpret_cast<const float4*>(v1);

        const float xp0 = fmaf(w1a.x, xn[0] * rinv, b1[0]);
        const float G   = xp0 * phi_cdf(xp0);

        const float W1f[5] = { G * w1a.x, G * w1a.y, G * w1a.z, G * w1a.w, G * w1e };
        const float V1f[4] = { G * v1a.x, G * v1a.y, G * v1a.z, G * v1a.w };
        const float u0 = (G * xp0) * nrm;        // homogenize the bias column

        // ---- bilinear on RAW x, all indices constexpr ----
        float gp[16], jn[16];
        Unroll<16>::run([&](auto K) {
            constexpr int k = decltype(K)::v;
            gp[k] = 0.f; jn[k] = 0.f;
        });

        Unroll<16>::run([&](auto J) {
            constexpr int j  = decltype(J)::v;
            constexpr int mb = I2M(j);
            constexpr int gB = pc4(mb);

            float uj;
            if constexpr (j == 0) {
                uj = u0;
            } else {
                uj = W1f[gB] * xn[j];
                if constexpr ((mb & 1) && gB < 4)
                    uj = fmaf(V1f[gB], xn[M2I(mb ^ 1)], uj);
            }

            Unroll<16>::run([&](auto I_) {
                constexpr int i  = decltype(I_)::v;
                constexpr int ma = I2M(i);
                if constexpr (!(ma & mb & 1)) {            // e0^2 = 0
                    constexpr int k = M2I(ma ^ mb);
                    if constexpr (msign(ma, mb) > 0) gp[k] = fmaf(xn[i],  uj, gp[k]);
                    else                             gp[k] = fmaf(xn[i], -uj, gp[k]);
                }
                if constexpr ((ma | mb) == 15) {           // join support
                    constexpr int k = M2I(ma & mb);
                    if constexpr (jsign(ma, mb) > 0) jn[k] = fmaf(xn[i],  uj, jn[k]);
                    else                             jn[k] = fmaf(xn[i], -uj, jn[k]);
                }
            });
        });

        // ---- output linears with normalization folded into the weights ----
        const float4 wga = *reinterpret_cast<const float4*>(wg);
        const float  wge = wg[4];
        const float4 vga = *reinterpret_cast<const float4*>(vg);
        const float4 wja = *reinterpret_cast<const float4*>(wj);
        const float  wje = wj[4];
        const float4 vja = *reinterpret_cast<const float4*>(vj);

        const float gfac = rinv2;                 // gp path scale
        const float jfac = xn[15] * rinv3;        // join path scale

        const float WG[5] = { wga.x * gfac, wga.y * gfac, wga.z * gfac,
                              wga.w * gfac, wge * gfac };
        const float VG[4] = { vga.x * gfac, vga.y * gfac, vga.z * gfac,
                              vga.w * gfac };
        const float WJ[5] = { wja.x * jfac, wja.y * jfac, wja.z * jfac,
                              wja.w * jfac, wje * jfac };
        const float VJ[4] = { vja.x * jfac, vja.y * jfac, vja.z * jfac,
                              vja.w * jfac };

        float o[16];
        Unroll<16>::run([&](auto D) {
            constexpr int d = decltype(D)::v;
            constexpr int m = I2M(d);
            constexpr int g = pc4(m);
            float v = fmaf(WG[g], gp[d], xn[d]);   // residual = raw x[d]
            v = fmaf(WJ[g], jn[d], v);
            if constexpr ((m & 1) && g < 4) {
                constexpr int sidx = M2I(m ^ 1);
                v = fmaf(VG[g], gp[sidx], v);
                v = fmaf(VJ[g], jn[sidx], v);
            }
            o[d] = v;
        });
        o[0] += bg[0] + bj[0];

        stage[swz(tid, 0)] = make_float4(o[0],  o[1],  o[2],  o[3]);
        stage[swz(tid, 1)] = make_float4(o[4],  o[5],  o[6],  o[7]);
        stage[swz(tid, 2)] = make_float4(o[8],  o[9],  o[10], o[11]);
        stage[swz(tid, 3)] = make_float4(o[12], o[13], o[14], o[15]);
    }
    __syncthreads();

    // ---- coalesced store from swizzled smem ----
    #pragma unroll
    for (int k = 0; k < 4; k++) {
        int f = tid + k * TPB;
        if (FULL || f < nf4) out4[f] = stage[swz(f >> 2, f & 3)];
    }
}

extern "C" void kernel_launch(void* const* d_in, const int* in_sizes, int n_in,
                              void* d_out, int out_size)
{
    const float* x  = (const float*)d_in[0];
    const float* w1 = (const float*)d_in[1];
    const float* v1 = (const float*)d_in[2];
    const float* b1 = (const float*)d_in[3];
    const float* wg = (const float*)d_in[4];
    const float* vg = (const float*)d_in[5];
    const float* bg = (const float*)d_in[6];
    const float* wj = (const float*)d_in[7];
    const float* vj = (const float*)d_in[8];
    const float* bj = (const float*)d_in[9];

    const int ntok   = in_sizes[0] / 16;
    const int blocks = (ntok + TPB - 1) / TPB;

    if (ntok % TPB == 0)
        mvffn_kernel<true><<<blocks, TPB>>>(x, w1, v1, b1, wg, vg, bg, wj, vj, bj,
                                            (float*)d_out, ntok);
    else
        mvffn_kernel<false><<<blocks, TPB>>>(x, w1, v1, b1, wg, vg, bg, wj, vj, bj,
                                             (float*)d_out, ntok);
}